// round 15
// baseline (speedup 1.0000x reference)
#include <cuda_runtime.h>
#include <cuda_bf16.h>
#include <cstdint>

#define B_   4
#define C_   2048
#define DM_  128
#define H_   8
#define DPH_ 16
#define K_   7
#define KRED (C_ * K_)          // 14336
#define KC_  64                 // K elems per smem chunk
#define NKC  (KRED / KC_)       // 224 chunks

// ---------------------------------------------------------------------------
// Global scratch (no allocation allowed in kernel_launch)
// ---------------------------------------------------------------------------
__device__ float g_kc[B_ * C_ * DM_];   // conv(key)   (b, c_out, l)
__device__ float g_vc[B_ * C_ * DM_];   // conv(value) (b, c_out, l)
__device__ float g_at[B_ * C_ * DM_];   // attention out merged heads

// im2col X operand, bf16 hi/lo planes, plain row layout:
// row = ((conv*4 + b)*2 + plane)*128 + n ; each row = KRED bf16 (k-contiguous)
__device__ __nv_bfloat16 g_Bim[2ull * 4 * 2 * 128 * KRED];

// ---------------------------------------------------------------------------
// Helpers
// ---------------------------------------------------------------------------
__device__ __forceinline__ unsigned smem_u32(const void* p) {
    return (unsigned)__cvta_generic_to_shared(p);
}

// ldmatrix x4 (non-transposed), 8x8 b16 tiles
#define LDSM4(r, addr)                                                        \
    asm volatile("ldmatrix.sync.aligned.m8n8.x4.shared.b16 {%0,%1,%2,%3}, [%4];" \
        : "=r"((r)[0]), "=r"((r)[1]), "=r"((r)[2]), "=r"((r)[3]) : "r"(addr))

// D += A * B, bf16 inputs, f32 accumulate
#define MMA16816(d, a, b0v, b1v)                                              \
    asm volatile("mma.sync.aligned.m16n8k16.row.col.f32.bf16.bf16.f32 "       \
        "{%0,%1,%2,%3}, {%4,%5,%6,%7}, {%8,%9}, {%0,%1,%2,%3};"               \
        : "+f"((d)[0]), "+f"((d)[1]), "+f"((d)[2]), "+f"((d)[3])              \
        : "r"((a)[0]), "r"((a)[1]), "r"((a)[2]), "r"((a)[3]),                 \
          "r"(b0v), "r"(b1v))

#define CP_COMMIT asm volatile("cp.async.commit_group;" ::: "memory")
#define CP_WAIT1  asm volatile("cp.async.wait_group 1;"  ::: "memory")
#define CP_WAIT0  asm volatile("cp.async.wait_group 0;"  ::: "memory")

// split (a,b) each into bf16 hi + bf16 lo residual, packed pairs (low 16b = a)
__device__ __forceinline__ void bsplit2(float a, float b, unsigned& h, unsigned& l) {
    __nv_bfloat162 h2 = __floats2bfloat162_rn(a, b);
    float ha = __low2float(h2), hb = __high2float(h2);
    __nv_bfloat162 l2 = __floats2bfloat162_rn(a - ha, b - hb);
    union { __nv_bfloat162 v; unsigned u; } uh, ul;
    uh.v = h2; ul.v = l2;
    h = uh.u; l = ul.u;
}

// ---------------------------------------------------------------------------
// Prepass: im2col X -> g_Bim, bf16 hi/lo planes, row layout [n][k].
// Xim[n][k] = X[b, ci, n + t - 6], k = ci*7 + t (0 for n+t<6).
// gid = (((conv*4+b)*128 + n)*1792 + g), thread writes 8 consecutive k (16B x2)
// ---------------------------------------------------------------------------
__global__ __launch_bounds__(256)
void im2col_prep(const float* __restrict__ key, const float* __restrict__ value)
{
    const int gid = blockIdx.x * 256 + threadIdx.x;   // < 1,835,008
    const int g    = gid % 1792;
    int rest       = gid / 1792;
    const int n    = rest & 127;
    rest >>= 7;
    const int b    = rest & 3;
    const int conv = rest >> 2;

    const float* Xb = (conv ? value : key) + (size_t)b * (C_ * DM_);

    union { unsigned short s[8]; uint4 v; } hu, lu;
    #pragma unroll
    for (int j = 0; j < 8; ++j) {
        const int k  = g * 8 + j;
        const int ci = k / 7;
        const int t  = k - ci * 7;
        const int xi = n + t - 6;
        const float val = (xi >= 0) ? Xb[ci * DM_ + xi] : 0.f;
        __nv_bfloat16 hb = __float2bfloat16_rn(val);
        __nv_bfloat16 lb = __float2bfloat16_rn(val - __bfloat162float(hb));
        union { __nv_bfloat16 b16; unsigned short u; } ch, cl;
        ch.b16 = hb; cl.b16 = lb;
        hu.s[j] = ch.u; lu.s[j] = cl.u;
    }

    const size_t rhi = ((size_t)((conv * 4 + b) * 2 + 0) * 128 + n) * KRED;
    const size_t rlo = ((size_t)((conv * 4 + b) * 2 + 1) * 128 + n) * KRED;
    ((uint4*)(g_Bim + rhi))[g] = hu.v;
    ((uint4*)(g_Bim + rlo))[g] = lu.v;
}

// ---------------------------------------------------------------------------
// Conv GEMM on mma.sync bf16 (3-product hi/lo split, f32 accum).
// Per CTA: M=128 (c_out tile), N=128 (full L), K=14336 in 224 chunks of 64.
// grid (16, 4, 2), 256 threads (8 warps x m16). Double-buffered smem stages:
//   Whi @0 | Wlo @18432 | Xhi @36864 | Xlo @55296   (rows pitch 144B, 128 rows)
// stage stride 73728, total dynamic smem 147456.
// ---------------------------------------------------------------------------
__global__ __launch_bounds__(256)
void conv_mma(const float* __restrict__ wk, const float* __restrict__ bk,
              const float* __restrict__ wv, const float* __restrict__ bv)
{
    extern __shared__ char smc[];
    const int tid = threadIdx.x, wid = tid >> 5, lane = tid & 31;
    const int conv = blockIdx.z, b = blockIdx.y, m0 = blockIdx.x * 128;

    const float* W    = (conv ? wv : wk) + (size_t)m0 * KRED;
    const float* bias = conv ? bv : bk;
    float* OUT        = (conv ? g_vc : g_kc) + (size_t)b * (C_ * DM_);
    const __nv_bfloat16* Xg = g_Bim + (size_t)((conv * 4 + b) * 2) * 128 * KRED;

    const int mrow_w = tid >> 1;      // W convert: this thread's m row
    const int half   = tid & 1;       // which 32-k half of the 64-k chunk

    auto load_chunk = [&](int kc, int s) {
        char* st = smc + s * 73728;
        // X: async copy of pre-converted bf16 planes (16KB total)
        #pragma unroll
        for (int i = 0; i < 8; ++i) {
            const int idx = tid + 256 * i;
            const int plane = idx >> 10;
            const int rr = idx & 1023, n = rr >> 3, g = rr & 7;
            const void* src = (const char*)(Xg + (size_t)plane * 128 * KRED
                                            + (size_t)n * KRED + kc * KC_) + g * 16;
            const unsigned dst = smem_u32(st + 36864 + plane * 18432 + n * 144 + g * 16);
            asm volatile("cp.async.cg.shared.global [%0], [%1], 16;"
                         :: "r"(dst), "l"(src));
        }
        CP_COMMIT;
        // W: load 32 f32, hi/lo split, store packed bf16 pairs
        const float4* src = (const float4*)(W + (size_t)mrow_w * KRED + kc * KC_ + half * 32);
        float4 f[8];
        #pragma unroll
        for (int i = 0; i < 8; ++i) f[i] = src[i];
        unsigned hi[16], lo[16];
        #pragma unroll
        for (int i = 0; i < 8; ++i) {
            bsplit2(f[i].x, f[i].y, hi[2 * i],     lo[2 * i]);
            bsplit2(f[i].z, f[i].w, hi[2 * i + 1], lo[2 * i + 1]);
        }
        char* Wh = st + mrow_w * 144 + half * 64;
        char* Wl = Wh + 18432;
        #pragma unroll
        for (int q = 0; q < 4; ++q) {
            *(uint4*)(Wh + q * 16) = make_uint4(hi[4*q], hi[4*q+1], hi[4*q+2], hi[4*q+3]);
            *(uint4*)(Wl + q * 16) = make_uint4(lo[4*q], lo[4*q+1], lo[4*q+2], lo[4*q+3]);
        }
    };

    // ldmatrix lane->address mapping (pitch 144B rows)
    const int r8 = lane & 7, gq = lane >> 3;
    const unsigned aoff = (unsigned)((wid * 16 + (gq & 1) * 8 + r8) * 144 + (gq >> 1) * 16);
    const unsigned boff = (unsigned)(((gq >> 1) * 8 + r8) * 144 + (gq & 1) * 16);

    float acc[16][4];
    #pragma unroll
    for (int nt = 0; nt < 16; ++nt)
        #pragma unroll
        for (int q = 0; q < 4; ++q) acc[nt][q] = 0.f;

    load_chunk(0, 0);

    for (int kc = 0; kc < NKC; ++kc) {
        if (kc + 1 < NKC) { load_chunk(kc + 1, (kc + 1) & 1); CP_WAIT1; }
        else              { CP_WAIT0; }
        __syncthreads();

        const unsigned sb = smem_u32(smc + (kc & 1) * 73728);
        #pragma unroll
        for (int ks = 0; ks < 4; ++ks) {        // 4 x k16 steps
            unsigned ah[4], al[4];
            LDSM4(ah, sb + aoff + ks * 32);
            LDSM4(al, sb + 18432 + aoff + ks * 32);
            #pragma unroll
            for (int ntp = 0; ntp < 8; ++ntp) { // 2 n-tiles per ldmatrix.x4
                unsigned bh[4], bl[4];
                LDSM4(bh, sb + 36864 + boff + ntp * 2304 + ks * 32);
                LDSM4(bl, sb + 55296 + boff + ntp * 2304 + ks * 32);
                MMA16816(acc[2 * ntp],     ah, bh[0], bh[1]);   // hi*hi
                MMA16816(acc[2 * ntp],     ah, bl[0], bl[1]);   // hi*lo
                MMA16816(acc[2 * ntp],     al, bh[0], bh[1]);   // lo*hi
                MMA16816(acc[2 * ntp + 1], ah, bh[2], bh[3]);
                MMA16816(acc[2 * ntp + 1], ah, bl[2], bl[3]);
                MMA16816(acc[2 * ntp + 1], al, bh[2], bh[3]);
            }
        }
        __syncthreads();
    }

    // Epilogue: c0,c1 -> (row, col 2q..2q+1), c2,c3 -> row+8
    const int rq = lane >> 2, cq = (lane & 3) * 2;
    const int mr = m0 + wid * 16 + rq;
    const float bb0 = bias[mr], bb1 = bias[mr + 8];
    float* o0 = OUT + (size_t)mr * DM_;
    float* o1 = OUT + (size_t)(mr + 8) * DM_;
    #pragma unroll
    for (int nt = 0; nt < 16; ++nt) {
        *(float2*)(o0 + nt * 8 + cq) = make_float2(acc[nt][0] + bb0, acc[nt][1] + bb0);
        *(float2*)(o1 + nt * 8 + cq) = make_float2(acc[nt][2] + bb1, acc[nt][3] + bb1);
    }
}

// ---------------------------------------------------------------------------
// Fast 2^y (fma pipe; avoids MUFU bottleneck on 134M exps). y <= 0 here.
// ---------------------------------------------------------------------------
__device__ __forceinline__ float fexp2(float y)
{
    y = fmaxf(y, -126.0f);
    const float n = rintf(y);
    const float f = y - n;
    float p = 1.3333558146e-3f;
    p = fmaf(p, f, 9.6181291076e-3f);
    p = fmaf(p, f, 5.5504108665e-2f);
    p = fmaf(p, f, 2.4022650696e-1f);
    p = fmaf(p, f, 6.9314718056e-1f);
    p = fmaf(p, f, 1.0f);
    const int ni = (int)n;
    return __int_as_float((ni + 127) << 23) * p;
}

// ---------------------------------------------------------------------------
// Flash-style attention, fp32. 1 thread = 1 query row. grid (C/128, H, B).
// ---------------------------------------------------------------------------
__global__ __launch_bounds__(128)
void attn_kernel(const float* __restrict__ query)
{
    const int b   = blockIdx.z;
    const int h   = blockIdx.y;
    const int tid = threadIdx.x;
    const int c   = blockIdx.x * 128 + tid;

    __shared__ float Ks[32][16];
    __shared__ float Vs[32][16];

    const float scale = 0.25f * 1.4426950408889634f;
    float q[16];
    {
        const float4* qp = (const float4*)(query + ((size_t)(b * C_) + c) * DM_ + h * DPH_);
        float4 q0 = qp[0], q1 = qp[1], q2 = qp[2], q3 = qp[3];
        q[0]=q0.x*scale; q[1]=q0.y*scale; q[2]=q0.z*scale; q[3]=q0.w*scale;
        q[4]=q1.x*scale; q[5]=q1.y*scale; q[6]=q1.z*scale; q[7]=q1.w*scale;
        q[8]=q2.x*scale; q[9]=q2.y*scale; q[10]=q2.z*scale; q[11]=q2.w*scale;
        q[12]=q3.x*scale; q[13]=q3.y*scale; q[14]=q3.z*scale; q[15]=q3.w*scale;
    }

    float acc[16];
    #pragma unroll
    for (int d = 0; d < 16; ++d) acc[d] = 0.f;
    float mmax = -3.0e38f, ssum = 0.f;

    const size_t kvbase = (size_t)(b * C_) * DM_ + h * DPH_;
    const int jrow = tid >> 2;
    const int d4   = (tid & 3) * 4;

    for (int kb = 0; kb < C_ / 32; ++kb) {
        __syncthreads();
        {
            const size_t idx = kvbase + (size_t)(kb * 32 + jrow) * DM_ + d4;
            *(float4*)&Ks[jrow][d4] = *(const float4*)(g_kc + idx);
            *(float4*)&Vs[jrow][d4] = *(const float4*)(g_vc + idx);
        }
        __syncthreads();

        float p[32];
        float cmax = -3.0e38f;
        #pragma unroll
        for (int j = 0; j < 32; ++j) {
            float4 k0 = *(const float4*)&Ks[j][0];
            float4 k1 = *(const float4*)&Ks[j][4];
            float4 k2 = *(const float4*)&Ks[j][8];
            float4 k3 = *(const float4*)&Ks[j][12];
            float s;
            s = q[0] * k0.x;
            s = fmaf(q[1],  k0.y, s); s = fmaf(q[2],  k0.z, s); s = fmaf(q[3],  k0.w, s);
            s = fmaf(q[4],  k1.x, s); s = fmaf(q[5],  k1.y, s); s = fmaf(q[6],  k1.z, s); s = fmaf(q[7],  k1.w, s);
            s = fmaf(q[8],  k2.x, s); s = fmaf(q[9],  k2.y, s); s = fmaf(q[10], k2.z, s); s = fmaf(q[11], k2.w, s);
            s = fmaf(q[12], k3.x, s); s = fmaf(q[13], k3.y, s); s = fmaf(q[14], k3.z, s); s = fmaf(q[15], k3.w, s);
            p[j] = s;
            cmax = fmaxf(cmax, s);
        }

        const float newm = fmaxf(mmax, cmax);
        const float corr = fexp2(mmax - newm);
        mmax = newm;
        ssum *= corr;
        #pragma unroll
        for (int d = 0; d < 16; ++d) acc[d] *= corr;

        #pragma unroll
        for (int j = 0; j < 32; ++j) {
            const float pj = fexp2(p[j] - newm);
            ssum += pj;
            float4 v0 = *(const float4*)&Vs[j][0];
            float4 v1 = *(const float4*)&Vs[j][4];
            float4 v2 = *(const float4*)&Vs[j][8];
            float4 v3 = *(const float4*)&Vs[j][12];
            acc[0]  = fmaf(pj, v0.x, acc[0]);  acc[1]  = fmaf(pj, v0.y, acc[1]);
            acc[2]  = fmaf(pj, v0.z, acc[2]);  acc[3]  = fmaf(pj, v0.w, acc[3]);
            acc[4]  = fmaf(pj, v1.x, acc[4]);  acc[5]  = fmaf(pj, v1.y, acc[5]);
            acc[6]  = fmaf(pj, v1.z, acc[6]);  acc[7]  = fmaf(pj, v1.w, acc[7]);
            acc[8]  = fmaf(pj, v2.x, acc[8]);  acc[9]  = fmaf(pj, v2.y, acc[9]);
            acc[10] = fmaf(pj, v2.z, acc[10]); acc[11] = fmaf(pj, v2.w, acc[11]);
            acc[12] = fmaf(pj, v3.x, acc[12]); acc[13] = fmaf(pj, v3.y, acc[13]);
            acc[14] = fmaf(pj, v3.z, acc[14]); acc[15] = fmaf(pj, v3.w, acc[15]);
        }
    }

    const float inv = 1.0f / ssum;
    float* op = g_at + ((size_t)(b * C_) + c) * DM_ + h * DPH_;
    #pragma unroll
    for (int d = 0; d < 16; d += 4) {
        float4 o = make_float4(acc[d] * inv, acc[d + 1] * inv, acc[d + 2] * inv, acc[d + 3] * inv);
        *(float4*)(op + d) = o;
    }
}

// ---------------------------------------------------------------------------
// Final linear: out[n,o] = sum_k g_at[n,k] * lin_w[o,k] + lin_b[o]
// ---------------------------------------------------------------------------
__global__ __launch_bounds__(128)
void linear_kernel(const float* __restrict__ lw, const float* __restrict__ lb,
                   float* __restrict__ out)
{
    const int row0 = blockIdx.x * 16;
    const int tid  = threadIdx.x;

    __shared__ float As[16][128];
    __shared__ float Ws[32][129];

    #pragma unroll
    for (int r = 0; r < 16; ++r)
        As[r][tid] = g_at[(size_t)(row0 + r) * DM_ + tid];

    float acc[16];
    #pragma unroll
    for (int r = 0; r < 16; ++r) acc[r] = 0.f;

    for (int k0 = 0; k0 < 128; k0 += 32) {
        __syncthreads();
        #pragma unroll
        for (int jj = 0; jj < 32; ++jj) {
            const int e = tid + 128 * jj;
            const int o = e >> 5, kk = e & 31;
            Ws[kk][o] = lw[o * 128 + k0 + kk];
        }
        __syncthreads();
        #pragma unroll
        for (int kk = 0; kk < 32; ++kk) {
            const float w = Ws[kk][tid];
            #pragma unroll
            for (int r = 0; r < 16; ++r)
                acc[r] = fmaf(As[r][k0 + kk], w, acc[r]);
        }
    }

    #pragma unroll
    for (int r = 0; r < 16; ++r)
        out[(size_t)(row0 + r) * DM_ + tid] = acc[r] + lb[tid];
}

// ---------------------------------------------------------------------------
extern "C" void kernel_launch(void* const* d_in, const int* in_sizes, int n_in,
                              void* d_out, int out_size)
{
    const float* query = (const float*)d_in[0];
    const float* key   = (const float*)d_in[1];
    const float* value = (const float*)d_in[2];
    const float* wk    = (const float*)d_in[3];
    const float* bk    = (const float*)d_in[4];
    const float* wv    = (const float*)d_in[5];
    const float* bv    = (const float*)d_in[6];
    const float* lw    = (const float*)d_in[7];
    const float* lb    = (const float*)d_in[8];
    float* out = (float*)d_out;

    cudaFuncSetAttribute(conv_mma, cudaFuncAttributeMaxDynamicSharedMemorySize, 147456);

    im2col_prep<<<7168, 256>>>(key, value);
    conv_mma<<<dim3(C_ / 128, B_, 2), 256, 147456>>>(wk, bk, wv, bv);
    attn_kernel<<<dim3(C_ / 128, H_, B_), 128>>>(query);
    linear_kernel<<<(B_ * C_) / 16, 128>>>(lw, lb, out);
}

// round 16
// speedup vs baseline: 1.0165x; 1.0165x over previous
#include <cuda_runtime.h>
#include <cuda_bf16.h>
#include <cstdint>

#define B_   4
#define C_   2048
#define DM_  128
#define H_   8
#define DPH_ 16
#define K_   7
#define KRED (C_ * K_)          // 14336
#define KC_  64                 // K elems per smem chunk
#define NKC  (KRED / KC_)       // 224 chunks

// ---------------------------------------------------------------------------
// Global scratch (no allocation allowed in kernel_launch)
// ---------------------------------------------------------------------------
__device__ float g_kc[B_ * C_ * DM_];   // conv(key)   (b, c_out, l)
__device__ float g_vc[B_ * C_ * DM_];   // conv(value) (b, c_out, l)
__device__ float g_at[B_ * C_ * DM_];   // attention out merged heads

// im2col X operand, bf16 hi/lo planes, plain row layout:
// row = ((conv*4 + b)*2 + plane)*128 + n ; each row = KRED bf16 (k-contiguous)
__device__ __nv_bfloat16 g_Bim[2ull * 4 * 2 * 128 * KRED];

// ---------------------------------------------------------------------------
// Helpers
// ---------------------------------------------------------------------------
__device__ __forceinline__ unsigned smem_u32(const void* p) {
    return (unsigned)__cvta_generic_to_shared(p);
}

// ldmatrix x4 (non-transposed), 8x8 b16 tiles
#define LDSM4(r, addr)                                                        \
    asm volatile("ldmatrix.sync.aligned.m8n8.x4.shared.b16 {%0,%1,%2,%3}, [%4];" \
        : "=r"((r)[0]), "=r"((r)[1]), "=r"((r)[2]), "=r"((r)[3]) : "r"(addr))

// D += A * B, bf16 inputs, f32 accumulate
#define MMA16816(d, a, b0v, b1v)                                              \
    asm volatile("mma.sync.aligned.m16n8k16.row.col.f32.bf16.bf16.f32 "       \
        "{%0,%1,%2,%3}, {%4,%5,%6,%7}, {%8,%9}, {%0,%1,%2,%3};"               \
        : "+f"((d)[0]), "+f"((d)[1]), "+f"((d)[2]), "+f"((d)[3])              \
        : "r"((a)[0]), "r"((a)[1]), "r"((a)[2]), "r"((a)[3]),                 \
          "r"(b0v), "r"(b1v))

#define CP_COMMIT asm volatile("cp.async.commit_group;" ::: "memory")
#define CP_WAIT1  asm volatile("cp.async.wait_group 1;"  ::: "memory")
#define CP_WAIT0  asm volatile("cp.async.wait_group 0;"  ::: "memory")

// split (a,b) each into bf16 hi + bf16 lo residual, packed pairs (low 16b = a)
__device__ __forceinline__ void bsplit2(float a, float b, unsigned& h, unsigned& l) {
    __nv_bfloat162 h2 = __floats2bfloat162_rn(a, b);
    float ha = __low2float(h2), hb = __high2float(h2);
    __nv_bfloat162 l2 = __floats2bfloat162_rn(a - ha, b - hb);
    union { __nv_bfloat162 v; unsigned u; } uh, ul;
    uh.v = h2; ul.v = l2;
    h = uh.u; l = ul.u;
}

// ---------------------------------------------------------------------------
// Prepass: im2col X -> g_Bim, bf16 hi/lo planes, row layout [n][k].
// Xim[n][k] = X[b, ci, n + t - 6], k = ci*7 + t (0 for n+t<6).
// gid = (((conv*4+b)*128 + n)*1792 + g), thread writes 8 consecutive k (16B x2)
// ---------------------------------------------------------------------------
__global__ __launch_bounds__(256)
void im2col_prep(const float* __restrict__ key, const float* __restrict__ value)
{
    const int gid = blockIdx.x * 256 + threadIdx.x;   // < 1,835,008
    const int g    = gid % 1792;
    int rest       = gid / 1792;
    const int n    = rest & 127;
    rest >>= 7;
    const int b    = rest & 3;
    const int conv = rest >> 2;

    const float* Xb = (conv ? value : key) + (size_t)b * (C_ * DM_);

    union { unsigned short s[8]; uint4 v; } hu, lu;
    #pragma unroll
    for (int j = 0; j < 8; ++j) {
        const int k  = g * 8 + j;
        const int ci = k / 7;
        const int t  = k - ci * 7;
        const int xi = n + t - 6;
        const float val = (xi >= 0) ? Xb[ci * DM_ + xi] : 0.f;
        __nv_bfloat16 hb = __float2bfloat16_rn(val);
        __nv_bfloat16 lb = __float2bfloat16_rn(val - __bfloat162float(hb));
        union { __nv_bfloat16 b16; unsigned short u; } ch, cl;
        ch.b16 = hb; cl.b16 = lb;
        hu.s[j] = ch.u; lu.s[j] = cl.u;
    }

    const size_t rhi = ((size_t)((conv * 4 + b) * 2 + 0) * 128 + n) * KRED;
    const size_t rlo = ((size_t)((conv * 4 + b) * 2 + 1) * 128 + n) * KRED;
    ((uint4*)(g_Bim + rhi))[g] = hu.v;
    ((uint4*)(g_Bim + rlo))[g] = lu.v;
}

// ---------------------------------------------------------------------------
// Conv GEMM on mma.sync bf16 (3-product hi/lo split, f32 accum).
// Per CTA: M=128 (c_out tile), N=128 (full L), K=14336 in 224 chunks of 64.
// grid (16, 4, 2), 256 threads (8 warps x m16). Double-buffered smem stages:
//   Whi @0 | Wlo @18432 | Xhi @36864 | Xlo @55296   (rows pitch 144B, 128 rows)
// stage stride 73728, total dynamic smem 147456.
// ---------------------------------------------------------------------------
__global__ __launch_bounds__(256)
void conv_mma(const float* __restrict__ wk, const float* __restrict__ bk,
              const float* __restrict__ wv, const float* __restrict__ bv)
{
    extern __shared__ char smc[];
    const int tid = threadIdx.x, wid = tid >> 5, lane = tid & 31;
    const int conv = blockIdx.z, b = blockIdx.y, m0 = blockIdx.x * 128;

    const float* W    = (conv ? wv : wk) + (size_t)m0 * KRED;
    const float* bias = conv ? bv : bk;
    float* OUT        = (conv ? g_vc : g_kc) + (size_t)b * (C_ * DM_);
    const __nv_bfloat16* Xg = g_Bim + (size_t)((conv * 4 + b) * 2) * 128 * KRED;

    const int mrow_w = tid >> 1;      // W convert: this thread's m row
    const int half   = tid & 1;       // which 32-k half of the 64-k chunk

    auto load_chunk = [&](int kc, int s) {
        char* st = smc + s * 73728;
        // X: async copy of pre-converted bf16 planes (16KB total)
        #pragma unroll
        for (int i = 0; i < 8; ++i) {
            const int idx = tid + 256 * i;
            const int plane = idx >> 10;
            const int rr = idx & 1023, n = rr >> 3, g = rr & 7;
            const void* src = (const char*)(Xg + (size_t)plane * 128 * KRED
                                            + (size_t)n * KRED + kc * KC_) + g * 16;
            const unsigned dst = smem_u32(st + 36864 + plane * 18432 + n * 144 + g * 16);
            asm volatile("cp.async.cg.shared.global [%0], [%1], 16;"
                         :: "r"(dst), "l"(src));
        }
        CP_COMMIT;
        // W: load 32 f32, hi/lo split, store packed bf16 pairs
        const float4* src = (const float4*)(W + (size_t)mrow_w * KRED + kc * KC_ + half * 32);
        float4 f[8];
        #pragma unroll
        for (int i = 0; i < 8; ++i) f[i] = src[i];
        unsigned hi[16], lo[16];
        #pragma unroll
        for (int i = 0; i < 8; ++i) {
            bsplit2(f[i].x, f[i].y, hi[2 * i],     lo[2 * i]);
            bsplit2(f[i].z, f[i].w, hi[2 * i + 1], lo[2 * i + 1]);
        }
        char* Wh = st + mrow_w * 144 + half * 64;
        char* Wl = Wh + 18432;
        #pragma unroll
        for (int q = 0; q < 4; ++q) {
            *(uint4*)(Wh + q * 16) = make_uint4(hi[4*q], hi[4*q+1], hi[4*q+2], hi[4*q+3]);
            *(uint4*)(Wl + q * 16) = make_uint4(lo[4*q], lo[4*q+1], lo[4*q+2], lo[4*q+3]);
        }
    };

    // ldmatrix lane->address mapping (pitch 144B rows)
    const int r8 = lane & 7, gq = lane >> 3;
    const unsigned aoff = (unsigned)((wid * 16 + (gq & 1) * 8 + r8) * 144 + (gq >> 1) * 16);
    const unsigned boff = (unsigned)(((gq >> 1) * 8 + r8) * 144 + (gq & 1) * 16);

    float acc[16][4];
    #pragma unroll
    for (int nt = 0; nt < 16; ++nt)
        #pragma unroll
        for (int q = 0; q < 4; ++q) acc[nt][q] = 0.f;

    load_chunk(0, 0);

    for (int kc = 0; kc < NKC; ++kc) {
        if (kc + 1 < NKC) { load_chunk(kc + 1, (kc + 1) & 1); CP_WAIT1; }
        else              { CP_WAIT0; }
        __syncthreads();

        const unsigned sb = smem_u32(smc + (kc & 1) * 73728);
        #pragma unroll
        for (int ks = 0; ks < 4; ++ks) {        // 4 x k16 steps
            unsigned ah[4], al[4];
            LDSM4(ah, sb + aoff + ks * 32);
            LDSM4(al, sb + 18432 + aoff + ks * 32);
            #pragma unroll
            for (int ntp = 0; ntp < 8; ++ntp) { // 2 n-tiles per ldmatrix.x4
                unsigned bh[4], bl[4];
                LDSM4(bh, sb + 36864 + boff + ntp * 2304 + ks * 32);
                LDSM4(bl, sb + 55296 + boff + ntp * 2304 + ks * 32);
                MMA16816(acc[2 * ntp],     ah, bh[0], bh[1]);   // hi*hi
                MMA16816(acc[2 * ntp],     ah, bl[0], bl[1]);   // hi*lo
                MMA16816(acc[2 * ntp],     al, bh[0], bh[1]);   // lo*hi
                MMA16816(acc[2 * ntp + 1], ah, bh[2], bh[3]);
                MMA16816(acc[2 * ntp + 1], ah, bl[2], bl[3]);
                MMA16816(acc[2 * ntp + 1], al, bh[2], bh[3]);
            }
        }
        __syncthreads();
    }

    // Epilogue: c0,c1 -> (row, col 2q..2q+1), c2,c3 -> row+8
    const int rq = lane >> 2, cq = (lane & 3) * 2;
    const int mr = m0 + wid * 16 + rq;
    const float bb0 = bias[mr], bb1 = bias[mr + 8];
    float* o0 = OUT + (size_t)mr * DM_;
    float* o1 = OUT + (size_t)(mr + 8) * DM_;
    #pragma unroll
    for (int nt = 0; nt < 16; ++nt) {
        *(float2*)(o0 + nt * 8 + cq) = make_float2(acc[nt][0] + bb0, acc[nt][1] + bb0);
        *(float2*)(o1 + nt * 8 + cq) = make_float2(acc[nt][2] + bb1, acc[nt][3] + bb1);
    }
}

// ---------------------------------------------------------------------------
// Fast 2^y (fma pipe; avoids MUFU bottleneck on 134M exps). y <= 0 here.
// ---------------------------------------------------------------------------
__device__ __forceinline__ float fexp2(float y)
{
    y = fmaxf(y, -126.0f);
    const float n = rintf(y);
    const float f = y - n;
    float p = 1.3333558146e-3f;
    p = fmaf(p, f, 9.6181291076e-3f);
    p = fmaf(p, f, 5.5504108665e-2f);
    p = fmaf(p, f, 2.4022650696e-1f);
    p = fmaf(p, f, 6.9314718056e-1f);
    p = fmaf(p, f, 1.0f);
    const int ni = (int)n;
    return __int_as_float((ni + 127) << 23) * p;
}

// ---------------------------------------------------------------------------
// Flash-style attention, fp32. 1 thread = 1 query row. grid (C/128, H, B).
// ---------------------------------------------------------------------------
__global__ __launch_bounds__(128)
void attn_kernel(const float* __restrict__ query)
{
    const int b   = blockIdx.z;
    const int h   = blockIdx.y;
    const int tid = threadIdx.x;
    const int c   = blockIdx.x * 128 + tid;

    __shared__ float Ks[32][16];
    __shared__ float Vs[32][16];

    const float scale = 0.25f * 1.4426950408889634f;
    float q[16];
    {
        const float4* qp = (const float4*)(query + ((size_t)(b * C_) + c) * DM_ + h * DPH_);
        float4 q0 = qp[0], q1 = qp[1], q2 = qp[2], q3 = qp[3];
        q[0]=q0.x*scale; q[1]=q0.y*scale; q[2]=q0.z*scale; q[3]=q0.w*scale;
        q[4]=q1.x*scale; q[5]=q1.y*scale; q[6]=q1.z*scale; q[7]=q1.w*scale;
        q[8]=q2.x*scale; q[9]=q2.y*scale; q[10]=q2.z*scale; q[11]=q2.w*scale;
        q[12]=q3.x*scale; q[13]=q3.y*scale; q[14]=q3.z*scale; q[15]=q3.w*scale;
    }

    float acc[16];
    #pragma unroll
    for (int d = 0; d < 16; ++d) acc[d] = 0.f;
    float mmax = -3.0e38f, ssum = 0.f;

    const size_t kvbase = (size_t)(b * C_) * DM_ + h * DPH_;
    const int jrow = tid >> 2;
    const int d4   = (tid & 3) * 4;

    for (int kb = 0; kb < C_ / 32; ++kb) {
        __syncthreads();
        {
            const size_t idx = kvbase + (size_t)(kb * 32 + jrow) * DM_ + d4;
            *(float4*)&Ks[jrow][d4] = *(const float4*)(g_kc + idx);
            *(float4*)&Vs[jrow][d4] = *(const float4*)(g_vc + idx);
        }
        __syncthreads();

        float p[32];
        float cmax = -3.0e38f;
        #pragma unroll
        for (int j = 0; j < 32; ++j) {
            float4 k0 = *(const float4*)&Ks[j][0];
            float4 k1 = *(const float4*)&Ks[j][4];
            float4 k2 = *(const float4*)&Ks[j][8];
            float4 k3 = *(const float4*)&Ks[j][12];
            float s;
            s = q[0] * k0.x;
            s = fmaf(q[1],  k0.y, s); s = fmaf(q[2],  k0.z, s); s = fmaf(q[3],  k0.w, s);
            s = fmaf(q[4],  k1.x, s); s = fmaf(q[5],  k1.y, s); s = fmaf(q[6],  k1.z, s); s = fmaf(q[7],  k1.w, s);
            s = fmaf(q[8],  k2.x, s); s = fmaf(q[9],  k2.y, s); s = fmaf(q[10], k2.z, s); s = fmaf(q[11], k2.w, s);
            s = fmaf(q[12], k3.x, s); s = fmaf(q[13], k3.y, s); s = fmaf(q[14], k3.z, s); s = fmaf(q[15], k3.w, s);
            p[j] = s;
            cmax = fmaxf(cmax, s);
        }

        const float newm = fmaxf(mmax, cmax);
        const float corr = fexp2(mmax - newm);
        mmax = newm;
        ssum *= corr;
        #pragma unroll
        for (int d = 0; d < 16; ++d) acc[d] *= corr;

        #pragma unroll
        for (int j = 0; j < 32; ++j) {
            const float pj = fexp2(p[j] - newm);
            ssum += pj;
            float4 v0 = *(const float4*)&Vs[j][0];
            float4 v1 = *(const float4*)&Vs[j][4];
            float4 v2 = *(const float4*)&Vs[j][8];
            float4 v3 = *(const float4*)&Vs[j][12];
            acc[0]  = fmaf(pj, v0.x, acc[0]);  acc[1]  = fmaf(pj, v0.y, acc[1]);
            acc[2]  = fmaf(pj, v0.z, acc[2]);  acc[3]  = fmaf(pj, v0.w, acc[3]);
            acc[4]  = fmaf(pj, v1.x, acc[4]);  acc[5]  = fmaf(pj, v1.y, acc[5]);
            acc[6]  = fmaf(pj, v1.z, acc[6]);  acc[7]  = fmaf(pj, v1.w, acc[7]);
            acc[8]  = fmaf(pj, v2.x, acc[8]);  acc[9]  = fmaf(pj, v2.y, acc[9]);
            acc[10] = fmaf(pj, v2.z, acc[10]); acc[11] = fmaf(pj, v2.w, acc[11]);
            acc[12] = fmaf(pj, v3.x, acc[12]); acc[13] = fmaf(pj, v3.y, acc[13]);
            acc[14] = fmaf(pj, v3.z, acc[14]); acc[15] = fmaf(pj, v3.w, acc[15]);
        }
    }

    const float inv = 1.0f / ssum;
    float* op = g_at + ((size_t)(b * C_) + c) * DM_ + h * DPH_;
    #pragma unroll
    for (int d = 0; d < 16; d += 4) {
        float4 o = make_float4(acc[d] * inv, acc[d + 1] * inv, acc[d + 2] * inv, acc[d + 3] * inv);
        *(float4*)(op + d) = o;
    }
}

// ---------------------------------------------------------------------------
// Final linear: out[n,o] = sum_k g_at[n,k] * lin_w[o,k] + lin_b[o]
// ---------------------------------------------------------------------------
__global__ __launch_bounds__(128)
void linear_kernel(const float* __restrict__ lw, const float* __restrict__ lb,
                   float* __restrict__ out)
{
    const int row0 = blockIdx.x * 16;
    const int tid  = threadIdx.x;

    __shared__ float As[16][128];
    __shared__ float Ws[32][129];

    #pragma unroll
    for (int r = 0; r < 16; ++r)
        As[r][tid] = g_at[(size_t)(row0 + r) * DM_ + tid];

    float acc[16];
    #pragma unroll
    for (int r = 0; r < 16; ++r) acc[r] = 0.f;

    for (int k0 = 0; k0 < 128; k0 += 32) {
        __syncthreads();
        #pragma unroll
        for (int jj = 0; jj < 32; ++jj) {
            const int e = tid + 128 * jj;
            const int o = e >> 5, kk = e & 31;
            Ws[kk][o] = lw[o * 128 + k0 + kk];
        }
        __syncthreads();
        #pragma unroll
        for (int kk = 0; kk < 32; ++kk) {
            const float w = Ws[kk][tid];
            #pragma unroll
            for (int r = 0; r < 16; ++r)
                acc[r] = fmaf(As[r][k0 + kk], w, acc[r]);
        }
    }

    #pragma unroll
    for (int r = 0; r < 16; ++r)
        out[(size_t)(row0 + r) * DM_ + tid] = acc[r] + lb[tid];
}

// ---------------------------------------------------------------------------
extern "C" void kernel_launch(void* const* d_in, const int* in_sizes, int n_in,
                              void* d_out, int out_size)
{
    const float* query = (const float*)d_in[0];
    const float* key   = (const float*)d_in[1];
    const float* value = (const float*)d_in[2];
    const float* wk    = (const float*)d_in[3];
    const float* bk    = (const float*)d_in[4];
    const float* wv    = (const float*)d_in[5];
    const float* bv    = (const float*)d_in[6];
    const float* lw    = (const float*)d_in[7];
    const float* lb    = (const float*)d_in[8];
    float* out = (float*)d_out;

    cudaFuncSetAttribute(conv_mma, cudaFuncAttributeMaxDynamicSharedMemorySize, 147456);

    im2col_prep<<<7168, 256>>>(key, value);
    conv_mma<<<dim3(C_ / 128, B_, 2), 256, 147456>>>(wk, bk, wv, bv);
    attn_kernel<<<dim3(C_ / 128, H_, B_), 128>>>(query);
    linear_kernel<<<(B_ * C_) / 16, 128>>>(lw, lb, out);
}